// round 5
// baseline (speedup 1.0000x reference)
#include <cuda_runtime.h>
#include <math.h>

#define BB 32
#define PP 24564
#define TT 20
#define CC 81

#define THRESH_HI 0.5f
#define THRESH_LO 0.4f
#define ALPHA     0.25f
#define VAR0      0.1f
#define VAR1      0.2f

#define NROWS      (BB * PP)          // 786048
#define TILE_ROWS  128
#define TILE_FLTS  (TILE_ROWS * CC)   // 10368 floats
#define TILE_BYTES (TILE_FLTS * 4)    // 41472
#define TILE_F4    (TILE_FLTS / 4)    // 2592
#define NTILES     (NROWS / TILE_ROWS)// 6141 (exact)
#define LBLK       128
#define LGRID      296                // 2 CTAs/SM on 148 SMs

// ---------------- device scratch (no allocations allowed) ----------------
__device__ unsigned long long g_best_prior[BB * TT]; // packed (iou_bits<<32)|(~p)
__device__ int   g_tgt[NROWS];        // packed: (tgt+1) in [0..81] low 8 | ti<<8
__device__ float g_part_l[LGRID];
__device__ float g_part_c[LGRID];
__device__ int   g_part_n[LGRID];

// ---------------- kernel 0: init ----------------
__global__ void init_kernel() {
    for (int i = threadIdx.x; i < BB * TT; i += blockDim.x)
        g_best_prior[i] = 0ull;
}

// ---- kernel 1: jaccard, 2 priors/thread; per-prior argmax over truths;
//      per-truth argmax over priors via REDUX max + REDUX min -------------
__global__ void match_kernel(const float* __restrict__ priors,
                             const float* __restrict__ targets) {
    __shared__ float s_t[TT][4];
    __shared__ float s_lab[TT];
    __shared__ unsigned long long s_key[TT];
    const int b   = blockIdx.y;
    const int tid = threadIdx.x;
    const int lane = tid & 31;

    if (tid < TT) {
        const float* tb = targets + (b * TT + tid) * 5;
        s_t[tid][0] = tb[0]; s_t[tid][1] = tb[1];
        s_t[tid][2] = tb[2]; s_t[tid][3] = tb[3];
        s_lab[tid]  = tb[4];
        s_key[tid]  = 0ull;
    }
    __syncthreads();

    const int p0 = blockIdx.x * 512 + 2 * tid;     // PP even -> pairs never split
    const bool ok = (p0 < PP);
    float4 pa = make_float4(0.5f, 0.5f, 0.1f, 0.1f);
    float4 pb = pa;
    if (ok) {
        pa = reinterpret_cast<const float4*>(priors)[p0];
        pb = reinterpret_cast<const float4*>(priors)[p0 + 1];
    }
    const float aax1 = pa.x - pa.z * 0.5f, aay1 = pa.y - pa.w * 0.5f;
    const float aax2 = pa.x + pa.z * 0.5f, aay2 = pa.y + pa.w * 0.5f;
    const float areaa = pa.z * pa.w;
    const float bax1 = pb.x - pb.z * 0.5f, bay1 = pb.y - pb.w * 0.5f;
    const float bax2 = pb.x + pb.z * 0.5f, bay2 = pb.y + pb.w * 0.5f;
    const float areab = pb.z * pb.w;

    float bo0 = -1.0f, bo1 = -1.0f;
    int   bt0 = 0,     bt1 = 0;

    #pragma unroll
    for (int t = 0; t < TT; t++) {
        const float tx1 = s_t[t][0], ty1 = s_t[t][1];
        const float tx2 = s_t[t][2], ty2 = s_t[t][3];
        const float areat = (tx2 - tx1) * (ty2 - ty1);

        float iw = fminf(aax2, tx2) - fmaxf(aax1, tx1);
        float ih = fminf(aay2, ty2) - fmaxf(aay1, ty1);
        iw = fmaxf(iw, 0.0f); ih = fmaxf(ih, 0.0f);
        const float in0  = iw * ih;
        const float iou0 = __fdividef(in0, areat + areaa - in0);

        iw = fminf(bax2, tx2) - fmaxf(bax1, tx1);
        ih = fminf(bay2, ty2) - fmaxf(bay1, ty1);
        iw = fmaxf(iw, 0.0f); ih = fmaxf(ih, 0.0f);
        const float in1  = iw * ih;
        const float iou1 = __fdividef(in1, areat + areab - in1);

        if (iou0 > bo0) { bo0 = iou0; bt0 = t; }
        if (iou1 > bo1) { bo1 = iou1; bt1 = t; }

        // warp argmax over 64 priors (iou >= 0 -> bits order-preserving)
        const unsigned u0 = ok ? __float_as_uint(iou0) : 0u;
        const unsigned u1 = ok ? __float_as_uint(iou1) : 0u;
        const unsigned m  = __reduce_max_sync(0xFFFFFFFFu, u0 > u1 ? u0 : u1);
        unsigned cand = 0xFFFFFFFFu;
        if (ok && u0 == m) cand = (unsigned)p0;
        if (ok && u1 == m && cand == 0xFFFFFFFFu) cand = (unsigned)(p0 + 1);
        const unsigned pmin = __reduce_min_sync(0xFFFFFFFFu, cand);
        if (lane == 0) {
            const unsigned long long key = (((unsigned long long)m) << 32)
                                         | (unsigned long long)(0xFFFFFFFFu - pmin);
            atomicMax(&s_key[t], key);
        }
    }

    if (ok) {
        int tgt0 = (int)s_lab[bt0] + 1;
        if (bo0 < THRESH_HI) tgt0 = -1;
        if (bo0 < THRESH_LO) tgt0 = 0;
        int tgt1 = (int)s_lab[bt1] + 1;
        if (bo1 < THRESH_HI) tgt1 = -1;
        if (bo1 < THRESH_LO) tgt1 = 0;
        int2 v;
        v.x = ((tgt0 + 1) & 0xFF) | (bt0 << 8);
        v.y = ((tgt1 + 1) & 0xFF) | (bt1 << 8);
        *reinterpret_cast<int2*>(g_tgt + b * PP + p0) = v;
    }
    __syncthreads();
    if (tid < TT) atomicMax(&g_best_prior[b * TT + tid], s_key[tid]);
}

// ---------------- kernel 2: force match (sequential per batch -> last-wins) ----
__global__ void force_kernel(const float* __restrict__ targets) {
    const int b = threadIdx.x;
    if (b < BB) {
        for (int t = 0; t < TT; t++) {
            unsigned long long key = g_best_prior[b * TT + t];
            unsigned p = 0xFFFFFFFFu - (unsigned)(key & 0xFFFFFFFFull);
            float lab = targets[(b * TT + t) * 5 + 4];
            g_tgt[b * PP + p] = (((int)lab + 2) & 0xFF) | (t << 8);
        }
    }
}

// ---- cp.async helpers ----
__device__ __forceinline__ void cp16(unsigned dst, const void* src) {
    asm volatile("cp.async.cg.shared.global [%0], [%1], 16;\n"
                 :: "r"(dst), "l"(src));
}
__device__ __forceinline__ void cp_commit() {
    asm volatile("cp.async.commit_group;\n");
}
template<int N>
__device__ __forceinline__ void cp_wait() {
    asm volatile("cp.async.wait_group %0;\n" :: "n"(N));
}

// ---- kernel 3: persistent, double-buffered focal + smooth-L1 --------------
__global__ void __launch_bounds__(LBLK, 2)
loss_kernel(const float* __restrict__ loc,
            const float* __restrict__ conf,
            const float* __restrict__ priors,
            const float* __restrict__ targets) {
    extern __shared__ float smem[];               // 2 * TILE_FLTS floats
    __shared__ float s_fl[LBLK / 32];
    __shared__ float s_ll[LBLK / 32];
    __shared__ int   s_np[LBLK / 32];

    const int tid  = threadIdx.x;
    const int lane = tid & 31;
    const int wid  = tid >> 5;
    const unsigned s_base = (unsigned)__cvta_generic_to_shared(smem);

    float fl = 0.0f, ll = 0.0f;
    int   np = 0;

    int tile = blockIdx.x;
    // prologue: stage tile 0 into buf 0
    {
        const char* src = (const char*)(conf) + (size_t)tile * TILE_BYTES;
        for (int i = tid; i < TILE_F4; i += LBLK)
            cp16(s_base + i * 16, src + i * 16);
        cp_commit();
    }
    int pk = g_tgt[tile * TILE_ROWS + tid];
    int buf = 0;

    while (tile < NTILES) {
        const int next = tile + LGRID;
        int pk_next = 0;
        if (next < NTILES) {
            const unsigned dbase = s_base + (buf ^ 1) * TILE_BYTES;
            const char* src = (const char*)(conf) + (size_t)next * TILE_BYTES;
            for (int i = tid; i < TILE_F4; i += LBLK)
                cp16(dbase + i * 16, src + i * 16);
            cp_commit();
            pk_next = g_tgt[next * TILE_ROWS + tid];
            cp_wait<1>();
        } else {
            cp_wait<0>();
        }
        __syncthreads();

        // compute current tile: thread-per-row, conflict-free LDS (81 mod 32 = 17)
        const float* myrow = smem + buf * TILE_FLTS + tid * CC;
        float sum = 0.0f;
        #pragma unroll 9
        for (int c = 0; c < CC; c++)
            sum += __expf(myrow[c]);

        const int tg = (pk & 0xFF) - 1;           // -1, 0, or 1..80
        if (tg >= 0) {                            // valid -> focal loss
            const float xt    = myrow[tg < 0 ? 0 : tg];
            const float lse   = __logf(sum);
            const float logpt = xt - lse;
            const float pt    = __expf(logpt);
            const float at    = (tg > 0) ? ALPHA : (1.0f - ALPHA);
            const float om    = 1.0f - pt;
            fl += -at * om * om * logpt;
        }
        if (tg > 0) {                             // positive (rare) -> smooth-L1
            np++;
            const int row = tile * TILE_ROWS + tid;
            const int b  = row / PP;
            const int p  = row - b * PP;
            const int ti = (pk >> 8) & 0xFF;
            const float* tb = targets + (b * TT + ti) * 5;
            const float tx1 = tb[0], ty1 = tb[1], tx2 = tb[2], ty2 = tb[3];
            const float4 pr = reinterpret_cast<const float4*>(priors)[p];

            const float gcx = ((tx1 + tx2) * 0.5f - pr.x) / (VAR0 * pr.z);
            const float gcy = ((ty1 + ty2) * 0.5f - pr.y) / (VAR0 * pr.w);
            const float gw  = __logf((tx2 - tx1) / pr.z) / VAR1;
            const float gh  = __logf((ty2 - ty1) / pr.w) / VAR1;

            const float4 ld = reinterpret_cast<const float4*>(loc)[row];
            const float d0 = ld.x - gcx, d1 = ld.y - gcy;
            const float d2 = ld.z - gw,  d3 = ld.w - gh;
            float ad;
            ad = fabsf(d0); ll += (ad < 1.0f) ? 0.5f * d0 * d0 : ad - 0.5f;
            ad = fabsf(d1); ll += (ad < 1.0f) ? 0.5f * d1 * d1 : ad - 0.5f;
            ad = fabsf(d2); ll += (ad < 1.0f) ? 0.5f * d2 * d2 : ad - 0.5f;
            ad = fabsf(d3); ll += (ad < 1.0f) ? 0.5f * d3 * d3 : ad - 0.5f;
        }

        __syncthreads();                          // all reads of buf done
        tile = next;
        pk   = pk_next;
        buf ^= 1;
    }

    // block reduction once
    #pragma unroll
    for (int off = 16; off > 0; off >>= 1) {
        fl += __shfl_xor_sync(0xFFFFFFFFu, fl, off);
        ll += __shfl_xor_sync(0xFFFFFFFFu, ll, off);
        np += __shfl_xor_sync(0xFFFFFFFFu, np, off);
    }
    if (lane == 0) { s_fl[wid] = fl; s_ll[wid] = ll; s_np[wid] = np; }
    __syncthreads();
    if (tid == 0) {
        float tc = 0.0f, tl = 0.0f; int tn = 0;
        #pragma unroll
        for (int i = 0; i < LBLK / 32; i++) { tc += s_fl[i]; tl += s_ll[i]; tn += s_np[i]; }
        g_part_c[blockIdx.x] = tc;
        g_part_l[blockIdx.x] = tl;
        g_part_n[blockIdx.x] = tn;
    }
}

// ---------------- kernel 4: deterministic final reduction ----------------
__global__ void final_kernel(float* __restrict__ out) {
    __shared__ double s_l[512];
    __shared__ double s_c[512];
    __shared__ int    s_n[512];
    const int tid = threadIdx.x;
    double tl = 0.0, tc = 0.0; int tn = 0;
    for (int i = tid; i < LGRID; i += 512) {
        tl += (double)g_part_l[i];
        tc += (double)g_part_c[i];
        tn += g_part_n[i];
    }
    s_l[tid] = tl; s_c[tid] = tc; s_n[tid] = tn;
    __syncthreads();
    for (int off = 256; off > 0; off >>= 1) {
        if (tid < off) {
            s_l[tid] += s_l[tid + off];
            s_c[tid] += s_c[tid + off];
            s_n[tid] += s_n[tid + off];
        }
        __syncthreads();
    }
    if (tid == 0) {
        const double n = (double)s_n[0];
        out[0] = (float)(s_l[0] / n);
        out[1] = (float)(s_c[0] / n);
    }
}

// ---------------- launch ----------------
extern "C" void kernel_launch(void* const* d_in, const int* in_sizes, int n_in,
                              void* d_out, int out_size) {
    const float* loc     = (const float*)d_in[0];   // (B,P,4)
    const float* conf    = (const float*)d_in[1];   // (B,P,81)
    const float* priors  = (const float*)d_in[2];   // (P,4)
    const float* targets = (const float*)d_in[3];   // (B,T,5)
    float* out = (float*)d_out;

    cudaFuncSetAttribute(loss_kernel,
                         cudaFuncAttributeMaxDynamicSharedMemorySize,
                         2 * TILE_BYTES);

    init_kernel<<<1, 256>>>();

    dim3 g1((PP + 511) / 512, BB);
    match_kernel<<<g1, 256>>>(priors, targets);

    force_kernel<<<1, 32>>>(targets);

    loss_kernel<<<LGRID, LBLK, 2 * TILE_BYTES>>>(loc, conf, priors, targets);

    final_kernel<<<1, 512>>>(out);
}

// round 6
// speedup vs baseline: 1.0201x; 1.0201x over previous
#include <cuda_runtime.h>
#include <math.h>

#define BB 32
#define PP 24564
#define TT 20
#define CC 81

#define THRESH_HI 0.5f
#define THRESH_LO 0.4f
#define ALPHA     0.25f
#define VAR0      0.1f
#define VAR1      0.2f

#define NROWS      (BB * PP)           // 786048
#define TILE_ROWS  128
#define TILE_FLTS  (TILE_ROWS * CC)    // 10368 floats (41472 B)
#define TILE_F4    (TILE_FLTS / 4)     // 2592
#define NTILES     (NROWS / TILE_ROWS) // 6141 (exact)
#define LBLK       512                 // 4 threads per row

// ---------------- device scratch (no allocations allowed) ----------------
__device__ unsigned long long g_best_prior[BB * TT]; // packed (iou_bits<<32)|(~p)
__device__ int   g_tgt[NROWS];         // packed: (tgt+1) in [0..81] low 8 | ti<<8
__device__ float g_part_l[NTILES];
__device__ float g_part_c[NTILES];
__device__ int   g_part_n[NTILES];

// ---------------- kernel 0: init ----------------
__global__ void init_kernel() {
    for (int i = threadIdx.x; i < BB * TT; i += blockDim.x)
        g_best_prior[i] = 0ull;
}

// ---- kernel 1: jaccard, 2 priors/thread; per-prior argmax over truths;
//      per-truth argmax over priors via REDUX max + ballot election -------
__global__ void match_kernel(const float* __restrict__ priors,
                             const float* __restrict__ targets) {
    __shared__ float s_t[TT][4];
    __shared__ float s_lab[TT];
    __shared__ unsigned long long s_key[TT];
    const int b    = blockIdx.y;
    const int tid  = threadIdx.x;
    const int lane = tid & 31;

    if (tid < TT) {
        const float* tb = targets + (b * TT + tid) * 5;
        s_t[tid][0] = tb[0]; s_t[tid][1] = tb[1];
        s_t[tid][2] = tb[2]; s_t[tid][3] = tb[3];
        s_lab[tid]  = tb[4];
        s_key[tid]  = 0ull;
    }
    __syncthreads();

    const int p0 = blockIdx.x * 512 + 2 * tid;     // PP even -> pairs never split
    const bool ok = (p0 < PP);
    float4 pa = make_float4(0.5f, 0.5f, 0.1f, 0.1f);
    float4 pb = pa;
    if (ok) {
        pa = reinterpret_cast<const float4*>(priors)[p0];
        pb = reinterpret_cast<const float4*>(priors)[p0 + 1];
    }
    const float aax1 = pa.x - pa.z * 0.5f, aay1 = pa.y - pa.w * 0.5f;
    const float aax2 = pa.x + pa.z * 0.5f, aay2 = pa.y + pa.w * 0.5f;
    const float areaa = pa.z * pa.w;
    const float bax1 = pb.x - pb.z * 0.5f, bay1 = pb.y - pb.w * 0.5f;
    const float bax2 = pb.x + pb.z * 0.5f, bay2 = pb.y + pb.w * 0.5f;
    const float areab = pb.z * pb.w;

    float bo0 = -1.0f, bo1 = -1.0f;
    int   bt0 = 0,     bt1 = 0;

    #pragma unroll
    for (int t = 0; t < TT; t++) {
        const float tx1 = s_t[t][0], ty1 = s_t[t][1];
        const float tx2 = s_t[t][2], ty2 = s_t[t][3];
        const float areat = (tx2 - tx1) * (ty2 - ty1);

        float iw = fminf(aax2, tx2) - fmaxf(aax1, tx1);
        float ih = fminf(aay2, ty2) - fmaxf(aay1, ty1);
        iw = fmaxf(iw, 0.0f); ih = fmaxf(ih, 0.0f);
        const float in0  = iw * ih;
        const float iou0 = __fdividef(in0, areat + areaa - in0);

        iw = fminf(bax2, tx2) - fmaxf(bax1, tx1);
        ih = fminf(bay2, ty2) - fmaxf(bay1, ty1);
        iw = fmaxf(iw, 0.0f); ih = fmaxf(ih, 0.0f);
        const float in1  = iw * ih;
        const float iou1 = __fdividef(in1, areat + areab - in1);

        if (iou0 > bo0) { bo0 = iou0; bt0 = t; }
        if (iou1 > bo1) { bo1 = iou1; bt1 = t; }

        // warp argmax over 64 priors (iou >= 0 -> bits order-preserving);
        // lowest matching lane holds the smallest matching prior index.
        const unsigned u0 = ok ? __float_as_uint(iou0) : 0u;
        const unsigned u1 = ok ? __float_as_uint(iou1) : 0u;
        const unsigned m  = __reduce_max_sync(0xFFFFFFFFu, u0 > u1 ? u0 : u1);
        const unsigned hit = __ballot_sync(0xFFFFFFFFu, ok && (u0 == m || u1 == m));
        if (lane == (__ffs(hit) - 1)) {
            const unsigned pmin = (u0 == m) ? (unsigned)p0 : (unsigned)(p0 + 1);
            const unsigned long long key = (((unsigned long long)m) << 32)
                                         | (unsigned long long)(0xFFFFFFFFu - pmin);
            atomicMax(&s_key[t], key);
        }
    }

    if (ok) {
        int tgt0 = (int)s_lab[bt0] + 1;
        if (bo0 < THRESH_HI) tgt0 = -1;
        if (bo0 < THRESH_LO) tgt0 = 0;
        int tgt1 = (int)s_lab[bt1] + 1;
        if (bo1 < THRESH_HI) tgt1 = -1;
        if (bo1 < THRESH_LO) tgt1 = 0;
        int2 v;
        v.x = ((tgt0 + 1) & 0xFF) | (bt0 << 8);
        v.y = ((tgt1 + 1) & 0xFF) | (bt1 << 8);
        *reinterpret_cast<int2*>(g_tgt + b * PP + p0) = v;
    }
    __syncthreads();
    if (tid < TT) atomicMax(&g_best_prior[b * TT + tid], s_key[tid]);
}

// ---------------- kernel 2: force match (sequential per batch -> last-wins) ----
__global__ void force_kernel(const float* __restrict__ targets) {
    const int b = threadIdx.x;
    if (b < BB) {
        for (int t = 0; t < TT; t++) {
            unsigned long long key = g_best_prior[b * TT + t];
            unsigned p = 0xFFFFFFFFu - (unsigned)(key & 0xFFFFFFFFull);
            float lab = targets[(b * TT + t) * 5 + 4];
            g_tgt[b * PP + p] = (((int)lab + 2) & 0xFF) | (t << 8);
        }
    }
}

// ------- kernel 3: focal + smooth-L1, 4 threads/row, 100% occupancy -----------
__global__ void __launch_bounds__(LBLK, 4)
loss_kernel(const float* __restrict__ loc,
            const float* __restrict__ conf,
            const float* __restrict__ priors,
            const float* __restrict__ targets) {
    __shared__ float tile[TILE_FLTS];            // 41472 B, row stride 81
    __shared__ float s_part[4 * TILE_ROWS];      // 2 KB quarter partials
    __shared__ float s_fl[LBLK / 32];
    __shared__ float s_ll[LBLK / 32];
    __shared__ int   s_np[LBLK / 32];

    const int tid  = threadIdx.x;
    const int lane = tid & 31;
    const int wid  = tid >> 5;
    const int row0 = blockIdx.x * TILE_ROWS;

    // coalesced float4 stage: block tile is contiguous in gmem
    {
        const float4* src = reinterpret_cast<const float4*>(conf + (size_t)row0 * CC);
        float4* dst = reinterpret_cast<float4*>(tile);
        for (int i = tid; i < TILE_F4; i += LBLK)
            dst[i] = src[i];
    }
    int pk = 0;
    if (tid < TILE_ROWS) pk = g_tgt[row0 + tid];   // coalesced 4B
    __syncthreads();

    // 4 threads per row: quarter q covers offsets {0:21, 21:20, 41:20, 61:20}
    const int r = tid & (TILE_ROWS - 1);
    const int q = tid >> 7;                        // warp-uniform
    const int off = (q == 0) ? 0 : (1 + q * 20);
    const float* myq = tile + r * CC + off;        // stride-81 rows: conflict-free
    float psum = 0.0f;
    #pragma unroll
    for (int c = 0; c < 20; c++)
        psum += __expf(myq[c]);
    if (q == 0) psum += __expf(myq[20]);
    s_part[q * TILE_ROWS + r] = psum;
    __syncthreads();

    float fl = 0.0f, ll = 0.0f;
    int   np = 0;

    if (tid < TILE_ROWS) {                         // quarter 0 runs the epilogue
        const float sum = s_part[tid] + s_part[TILE_ROWS + tid]
                        + s_part[2 * TILE_ROWS + tid] + s_part[3 * TILE_ROWS + tid];
        const int tg = (pk & 0xFF) - 1;            // -1, 0, or 1..80
        if (tg >= 0) {                             // valid -> focal loss
            const float xt    = tile[tid * CC + (tg < 0 ? 0 : tg)];
            const float lse   = __logf(sum);
            const float logpt = xt - lse;
            const float pt    = __expf(logpt);
            const float at    = (tg > 0) ? ALPHA : (1.0f - ALPHA);
            const float om    = 1.0f - pt;
            fl = -at * om * om * logpt;
        }
        if (tg > 0) {                              // positive (rare) -> smooth-L1
            np = 1;
            const int row = row0 + tid;
            const int b  = row / PP;
            const int p  = row - b * PP;
            const int ti = (pk >> 8) & 0xFF;
            const float* tb = targets + (b * TT + ti) * 5;
            const float tx1 = tb[0], ty1 = tb[1], tx2 = tb[2], ty2 = tb[3];
            const float4 pr = reinterpret_cast<const float4*>(priors)[p];

            const float gcx = ((tx1 + tx2) * 0.5f - pr.x) / (VAR0 * pr.z);
            const float gcy = ((ty1 + ty2) * 0.5f - pr.y) / (VAR0 * pr.w);
            const float gw  = __logf((tx2 - tx1) / pr.z) / VAR1;
            const float gh  = __logf((ty2 - ty1) / pr.w) / VAR1;

            const float4 ld = reinterpret_cast<const float4*>(loc)[row];
            const float d0 = ld.x - gcx, d1 = ld.y - gcy;
            const float d2 = ld.z - gw,  d3 = ld.w - gh;
            float ad;
            ad = fabsf(d0); ll += (ad < 1.0f) ? 0.5f * d0 * d0 : ad - 0.5f;
            ad = fabsf(d1); ll += (ad < 1.0f) ? 0.5f * d1 * d1 : ad - 0.5f;
            ad = fabsf(d2); ll += (ad < 1.0f) ? 0.5f * d2 * d2 : ad - 0.5f;
            ad = fabsf(d3); ll += (ad < 1.0f) ? 0.5f * d3 * d3 : ad - 0.5f;
        }
    }

    // block reduction (threads >= 128 contribute zeros)
    #pragma unroll
    for (int offs = 16; offs > 0; offs >>= 1) {
        fl += __shfl_xor_sync(0xFFFFFFFFu, fl, offs);
        ll += __shfl_xor_sync(0xFFFFFFFFu, ll, offs);
        np += __shfl_xor_sync(0xFFFFFFFFu, np, offs);
    }
    if (lane == 0) { s_fl[wid] = fl; s_ll[wid] = ll; s_np[wid] = np; }
    __syncthreads();
    if (tid == 0) {
        float tc = 0.0f, tl = 0.0f; int tn = 0;
        #pragma unroll
        for (int i = 0; i < LBLK / 32; i++) { tc += s_fl[i]; tl += s_ll[i]; tn += s_np[i]; }
        g_part_c[blockIdx.x] = tc;
        g_part_l[blockIdx.x] = tl;
        g_part_n[blockIdx.x] = tn;
    }
}

// ---------------- kernel 4: deterministic final reduction ----------------
__global__ void final_kernel(float* __restrict__ out) {
    __shared__ double s_l[1024];
    __shared__ double s_c[1024];
    __shared__ int    s_n[1024];
    const int tid = threadIdx.x;
    double tl = 0.0, tc = 0.0; int tn = 0;
    for (int i = tid; i < NTILES; i += 1024) {
        tl += (double)g_part_l[i];
        tc += (double)g_part_c[i];
        tn += g_part_n[i];
    }
    s_l[tid] = tl; s_c[tid] = tc; s_n[tid] = tn;
    __syncthreads();
    for (int off = 512; off > 0; off >>= 1) {
        if (tid < off) {
            s_l[tid] += s_l[tid + off];
            s_c[tid] += s_c[tid + off];
            s_n[tid] += s_n[tid + off];
        }
        __syncthreads();
    }
    if (tid == 0) {
        const double n = (double)s_n[0];
        out[0] = (float)(s_l[0] / n);
        out[1] = (float)(s_c[0] / n);
    }
}

// ---------------- launch ----------------
extern "C" void kernel_launch(void* const* d_in, const int* in_sizes, int n_in,
                              void* d_out, int out_size) {
    const float* loc     = (const float*)d_in[0];   // (B,P,4)
    const float* conf    = (const float*)d_in[1];   // (B,P,81)
    const float* priors  = (const float*)d_in[2];   // (P,4)
    const float* targets = (const float*)d_in[3];   // (B,T,5)
    float* out = (float*)d_out;

    init_kernel<<<1, 256>>>();

    dim3 g1((PP + 511) / 512, BB);
    match_kernel<<<g1, 256>>>(priors, targets);

    force_kernel<<<1, 32>>>(targets);

    loss_kernel<<<NTILES, LBLK>>>(loc, conf, priors, targets);

    final_kernel<<<1, 1024>>>(out);
}

// round 9
// speedup vs baseline: 1.2954x; 1.2698x over previous
#include <cuda_runtime.h>
#include <math.h>

#define BB 32
#define PP 24564
#define TT 20
#define CC 81

#define THRESH_HI 0.5f
#define THRESH_LO 0.4f
#define ALPHA     0.25f
#define VAR0      0.1f
#define VAR1      0.2f

#define NROWS      (BB * PP)           // 786048
#define TILE_ROWS  128                 // per block
#define TILE_FLTS  (TILE_ROWS * CC)    // 10368 floats (41472 B)
#define TILE_BYTES (TILE_FLTS * 4)
#define NTILES     (NROWS / TILE_ROWS) // 6141 (exact)
#define LBLK       256                 // 8 warps, 16 rows per warp
#define RPWARP     16
#define CHUNK_FLTS (RPWARP * CC)       // 1296
#define CHUNK_F4   (CHUNK_FLTS / 4)    // 324 (chunks are 5184 B, 16B-aligned)

// ---------------- device scratch (no allocations allowed) ----------------
__device__ unsigned long long g_best_prior[BB * TT]; // packed (iou_bits<<32)|(~p)
__device__ int   g_tgt[NROWS];         // packed: (tgt+1) in [0..81] low 8 | ti<<8
__device__ float g_part_l[NTILES];
__device__ float g_part_c[NTILES];
__device__ int   g_part_n[NTILES];

// ---------------- kernel 0: init ----------------
__global__ void init_kernel() {
    for (int i = threadIdx.x; i < BB * TT; i += blockDim.x)
        g_best_prior[i] = 0ull;
}

// ---- kernel 1: jaccard, 2 priors/thread; per-prior argmax over truths;
//      per-truth argmax over priors via REDUX max + ballot election -------
__global__ void match_kernel(const float* __restrict__ priors,
                             const float* __restrict__ targets) {
    __shared__ float s_t[TT][4];
    __shared__ float s_lab[TT];
    __shared__ unsigned long long s_key[TT];
    const int b    = blockIdx.y;
    const int tid  = threadIdx.x;
    const int lane = tid & 31;

    if (tid < TT) {
        const float* tb = targets + (b * TT + tid) * 5;
        s_t[tid][0] = tb[0]; s_t[tid][1] = tb[1];
        s_t[tid][2] = tb[2]; s_t[tid][3] = tb[3];
        s_lab[tid]  = tb[4];
        s_key[tid]  = 0ull;
    }
    __syncthreads();

    const int p0 = blockIdx.x * 512 + 2 * tid;     // PP even -> pairs never split
    const bool ok = (p0 < PP);
    float4 pa = make_float4(0.5f, 0.5f, 0.1f, 0.1f);
    float4 pb = pa;
    if (ok) {
        pa = reinterpret_cast<const float4*>(priors)[p0];
        pb = reinterpret_cast<const float4*>(priors)[p0 + 1];
    }
    const float aax1 = pa.x - pa.z * 0.5f, aay1 = pa.y - pa.w * 0.5f;
    const float aax2 = pa.x + pa.z * 0.5f, aay2 = pa.y + pa.w * 0.5f;
    const float areaa = pa.z * pa.w;
    const float bax1 = pb.x - pb.z * 0.5f, bay1 = pb.y - pb.w * 0.5f;
    const float bax2 = pb.x + pb.z * 0.5f, bay2 = pb.y + pb.w * 0.5f;
    const float areab = pb.z * pb.w;

    float bo0 = -1.0f, bo1 = -1.0f;
    int   bt0 = 0,     bt1 = 0;

    #pragma unroll
    for (int t = 0; t < TT; t++) {
        const float tx1 = s_t[t][0], ty1 = s_t[t][1];
        const float tx2 = s_t[t][2], ty2 = s_t[t][3];
        const float areat = (tx2 - tx1) * (ty2 - ty1);

        float iw = fminf(aax2, tx2) - fmaxf(aax1, tx1);
        float ih = fminf(aay2, ty2) - fmaxf(aay1, ty1);
        iw = fmaxf(iw, 0.0f); ih = fmaxf(ih, 0.0f);
        const float in0  = iw * ih;
        const float iou0 = __fdividef(in0, areat + areaa - in0);

        iw = fminf(bax2, tx2) - fmaxf(bax1, tx1);
        ih = fminf(bay2, ty2) - fmaxf(bay1, ty1);
        iw = fmaxf(iw, 0.0f); ih = fmaxf(ih, 0.0f);
        const float in1  = iw * ih;
        const float iou1 = __fdividef(in1, areat + areab - in1);

        if (iou0 > bo0) { bo0 = iou0; bt0 = t; }
        if (iou1 > bo1) { bo1 = iou1; bt1 = t; }

        // warp argmax over 64 priors (iou >= 0 -> bits order-preserving);
        // lowest matching lane holds the smallest matching prior index.
        const unsigned u0 = ok ? __float_as_uint(iou0) : 0u;
        const unsigned u1 = ok ? __float_as_uint(iou1) : 0u;
        const unsigned m  = __reduce_max_sync(0xFFFFFFFFu, u0 > u1 ? u0 : u1);
        const unsigned hit = __ballot_sync(0xFFFFFFFFu, ok && (u0 == m || u1 == m));
        if (lane == (__ffs(hit) - 1)) {
            const unsigned pmin = (u0 == m) ? (unsigned)p0 : (unsigned)(p0 + 1);
            const unsigned long long key = (((unsigned long long)m) << 32)
                                         | (unsigned long long)(0xFFFFFFFFu - pmin);
            atomicMax(&s_key[t], key);
        }
    }

    if (ok) {
        int tgt0 = (int)s_lab[bt0] + 1;
        if (bo0 < THRESH_HI) tgt0 = -1;
        if (bo0 < THRESH_LO) tgt0 = 0;
        int tgt1 = (int)s_lab[bt1] + 1;
        if (bo1 < THRESH_HI) tgt1 = -1;
        if (bo1 < THRESH_LO) tgt1 = 0;
        int2 v;
        v.x = ((tgt0 + 1) & 0xFF) | (bt0 << 8);
        v.y = ((tgt1 + 1) & 0xFF) | (bt1 << 8);
        *reinterpret_cast<int2*>(g_tgt + b * PP + p0) = v;
    }
    __syncthreads();
    if (tid < TT) atomicMax(&g_best_prior[b * TT + tid], s_key[tid]);
}

// ---------------- kernel 2: force match (sequential per batch -> last-wins) ----
__global__ void force_kernel(const float* __restrict__ targets) {
    const int b = threadIdx.x;
    if (b < BB) {
        for (int t = 0; t < TT; t++) {
            unsigned long long key = g_best_prior[b * TT + t];
            unsigned p = 0xFFFFFFFFu - (unsigned)(key & 0xFFFFFFFFull);
            float lab = targets[(b * TT + t) * 5 + 4];
            g_tgt[b * PP + p] = (((int)lab + 2) & 0xFF) | (t << 8);
        }
    }
}

// ---- cp.async helpers ----
__device__ __forceinline__ void cp16(unsigned dst, const void* src) {
    asm volatile("cp.async.cg.shared.global [%0], [%1], 16;\n"
                 :: "r"(dst), "l"(src));
}
__device__ __forceinline__ void cp_commit() {
    asm volatile("cp.async.commit_group;\n");
}
template<int N>
__device__ __forceinline__ void cp_wait() {
    asm volatile("cp.async.wait_group %0;\n" :: "n"(N));
}

// ---- kernel 3: warp-autonomous focal + smooth-L1 (no block barriers) --------
// tile lives in DYNAMIC smem (guaranteed 16B-aligned; scaffold proven in R5)
__global__ void __launch_bounds__(LBLK, 5)
loss_kernel(const float* __restrict__ loc,
            const float* __restrict__ conf,
            const float* __restrict__ priors,
            const float* __restrict__ targets) {
    extern __shared__ float tile[];              // TILE_FLTS floats
    __shared__ float s_fl[LBLK / 32];
    __shared__ float s_ll[LBLK / 32];
    __shared__ int   s_np[LBLK / 32];

    const int tid  = threadIdx.x;
    const int lane = tid & 31;
    const int wid  = tid >> 5;
    const int wrow0 = blockIdx.x * TILE_ROWS + wid * RPWARP;   // warp's 16 rows

    // warp-private cp.async stage of its 5184B chunk
    const unsigned sbase = (unsigned)__cvta_generic_to_shared(tile)
                         + wid * CHUNK_FLTS * 4;
    {
        const char* src = (const char*)conf + (size_t)wrow0 * CC * 4;
        #pragma unroll
        for (int i = lane; i < CHUNK_F4; i += 32)
            cp16(sbase + i * 16, src + i * 16);
        cp_commit();
    }

    const int r = lane >> 1;                      // 0..15 (row within chunk)
    const int h = lane & 1;                       // half: 0 -> 41 elems, 1 -> 40
    const int myrow = wrow0 + r;
    const int pk = g_tgt[myrow];                  // overlaps cp.async in flight

    cp_wait<0>();
    __syncwarp();

    const float* my = tile + wid * CHUNK_FLTS + r * CC + h * 41;
    float psum = 0.0f;
    #pragma unroll 8
    for (int c = 0; c < 40; c++)
        psum += __expf(my[c]);
    if (h == 0) psum += __expf(my[40]);
    psum += __shfl_xor_sync(0xFFFFFFFFu, psum, 1);   // pair sum -> full row sum

    float fl = 0.0f, ll = 0.0f;
    int   np = 0;

    if (h == 0) {                                  // even lane runs epilogue
        const int tg = (pk & 0xFF) - 1;            // -1, 0, or 1..80
        if (tg >= 0) {                             // valid -> focal loss
            const float xt    = tile[wid * CHUNK_FLTS + r * CC + (tg < 0 ? 0 : tg)];
            const float lse   = __logf(psum);
            const float logpt = xt - lse;
            const float pt    = __expf(logpt);
            const float at    = (tg > 0) ? ALPHA : (1.0f - ALPHA);
            const float om    = 1.0f - pt;
            fl = -at * om * om * logpt;
        }
        if (tg > 0) {                              // positive (rare) -> smooth-L1
            np = 1;
            const int b  = myrow / PP;
            const int p  = myrow - b * PP;
            const int ti = (pk >> 8) & 0xFF;
            const float* tb = targets + (b * TT + ti) * 5;
            const float tx1 = tb[0], ty1 = tb[1], tx2 = tb[2], ty2 = tb[3];
            const float4 pr = reinterpret_cast<const float4*>(priors)[p];

            const float gcx = ((tx1 + tx2) * 0.5f - pr.x) / (VAR0 * pr.z);
            const float gcy = ((ty1 + ty2) * 0.5f - pr.y) / (VAR0 * pr.w);
            const float gw  = __logf((tx2 - tx1) / pr.z) / VAR1;
            const float gh  = __logf((ty2 - ty1) / pr.w) / VAR1;

            const float4 ld = reinterpret_cast<const float4*>(loc)[myrow];
            const float d0 = ld.x - gcx, d1 = ld.y - gcy;
            const float d2 = ld.z - gw,  d3 = ld.w - gh;
            float ad;
            ad = fabsf(d0); ll += (ad < 1.0f) ? 0.5f * d0 * d0 : ad - 0.5f;
            ad = fabsf(d1); ll += (ad < 1.0f) ? 0.5f * d1 * d1 : ad - 0.5f;
            ad = fabsf(d2); ll += (ad < 1.0f) ? 0.5f * d2 * d2 : ad - 0.5f;
            ad = fabsf(d3); ll += (ad < 1.0f) ? 0.5f * d3 * d3 : ad - 0.5f;
        }
    }

    // warp butterfly, then one barrier for the block total
    #pragma unroll
    for (int off = 16; off > 0; off >>= 1) {
        fl += __shfl_xor_sync(0xFFFFFFFFu, fl, off);
        ll += __shfl_xor_sync(0xFFFFFFFFu, ll, off);
        np += __shfl_xor_sync(0xFFFFFFFFu, np, off);
    }
    if (lane == 0) { s_fl[wid] = fl; s_ll[wid] = ll; s_np[wid] = np; }
    __syncthreads();
    if (tid == 0) {
        float tc = 0.0f, tl = 0.0f; int tn = 0;
        #pragma unroll
        for (int i = 0; i < LBLK / 32; i++) { tc += s_fl[i]; tl += s_ll[i]; tn += s_np[i]; }
        g_part_c[blockIdx.x] = tc;
        g_part_l[blockIdx.x] = tl;
        g_part_n[blockIdx.x] = tn;
    }
}

// ---------------- kernel 4: deterministic final reduction ----------------
__global__ void final_kernel(float* __restrict__ out) {
    __shared__ double s_l[1024];
    __shared__ double s_c[1024];
    __shared__ int    s_n[1024];
    const int tid = threadIdx.x;
    double tl = 0.0, tc = 0.0; int tn = 0;
    for (int i = tid; i < NTILES; i += 1024) {
        tl += (double)g_part_l[i];
        tc += (double)g_part_c[i];
        tn += g_part_n[i];
    }
    s_l[tid] = tl; s_c[tid] = tc; s_n[tid] = tn;
    __syncthreads();
    for (int off = 512; off > 0; off >>= 1) {
        if (tid < off) {
            s_l[tid] += s_l[tid + off];
            s_c[tid] += s_c[tid + off];
            s_n[tid] += s_n[tid + off];
        }
        __syncthreads();
    }
    if (tid == 0) {
        const double n = (double)s_n[0];
        out[0] = (float)(s_l[0] / n);
        out[1] = (float)(s_c[0] / n);
    }
}

// ---------------- launch ----------------
extern "C" void kernel_launch(void* const* d_in, const int* in_sizes, int n_in,
                              void* d_out, int out_size) {
    const float* loc     = (const float*)d_in[0];   // (B,P,4)
    const float* conf    = (const float*)d_in[1];   // (B,P,81)
    const float* priors  = (const float*)d_in[2];   // (P,4)
    const float* targets = (const float*)d_in[3];   // (B,T,5)
    float* out = (float*)d_out;

    cudaFuncSetAttribute(loss_kernel,
                         cudaFuncAttributeMaxDynamicSharedMemorySize,
                         TILE_BYTES);

    init_kernel<<<1, 256>>>();

    dim3 g1((PP + 511) / 512, BB);
    match_kernel<<<g1, 256>>>(priors, targets);

    force_kernel<<<1, 32>>>(targets);

    loss_kernel<<<NTILES, LBLK, TILE_BYTES>>>(loc, conf, priors, targets);

    final_kernel<<<1, 1024>>>(out);
}